// round 13
// baseline (speedup 1.0000x reference)
#include <cuda_runtime.h>
#include <cstdint>

#define NN 1024
#define DD 128
#define HH 64
#define BB 2

// Scratch (device globals: no allocation allowed in kernel_launch)
__device__ float g_AI[BB * NN * HH];              // [bn][h]
__device__ float g_AJ[BB * (HH / 2) * NN * 2];    // [b][hp][n][2]  (h-pair-major, packed)

// ---------------------------------------------------------------------------
// Kernel A: projections.  AI[bn][h] = emb[bn]·Wi[h],  AJ[b][hp][n] = emb·Wj + b1
// grid 128 x 512 threads; 16 rows/block.  Thread (o = tid>>2, dq = tid&3):
// o = 0..127 output (part=o>>6, h=o&63), dq = quarter of the 128-d dot.
// W1 read exactly once per block (64 KB) -> 8 MB total L2 traffic.
// ---------------------------------------------------------------------------
__global__ __launch_bounds__(512) void proj_kernel(const float* __restrict__ emb,
                                                   const float* __restrict__ W1,
                                                   const float* __restrict__ b1)
{
    __shared__ float emb_s[16 * 128];
    const int tid = threadIdx.x;
    const int bn0 = blockIdx.x * 16;

    {
        const float4* src = (const float4*)(emb + (size_t)bn0 * DD);
        ((float4*)emb_s)[tid] = src[tid];          // 16*128/4 = 512 float4
    }

    const int o = tid >> 2;          // 0..127
    const int dq = tid & 3;          // d-quarter (32 floats)
    const int part = o >> 6;         // 0 -> Wi/AI, 1 -> Wj/AJ
    const int h = o & 63;

    float4 w1r[8];
    const float4* wsrc = (const float4*)(W1 + h * (2 * DD) + part * DD + dq * 32);
#pragma unroll
    for (int i = 0; i < 8; i++) w1r[i] = wsrc[i];

    __syncthreads();

    const float b1v = b1[h];
#pragma unroll
    for (int nl = 0; nl < 16; nl++) {
        const float4* er = (const float4*)(emb_s + nl * 128 + dq * 32);
        float a0 = 0.f, a1 = 0.f, a2 = 0.f, a3 = 0.f;
#pragma unroll
        for (int i = 0; i < 8; i++) {
            float4 e = er[i], w = w1r[i];
            a0 = fmaf(e.x, w.x, a0);
            a1 = fmaf(e.y, w.y, a1);
            a2 = fmaf(e.z, w.z, a2);
            a3 = fmaf(e.w, w.w, a3);
        }
        float acc = (a0 + a1) + (a2 + a3);
        acc += __shfl_xor_sync(0xffffffffu, acc, 1);
        acc += __shfl_xor_sync(0xffffffffu, acc, 2);
        if (dq == 0) {
            const int bn = bn0 + nl;
            if (part == 0) {
                g_AI[bn * HH + h] = acc;
            } else {
                const int b = bn >> 10, n = bn & (NN - 1);
                g_AJ[(((b * (HH / 2)) + (h >> 1)) * NN + n) * 2 + (h & 1)] = acc + b1v;
            }
        }
    }
}

// ---------------------------------------------------------------------------
// Kernel B (fused): edge weights + mask + row softmax.
// Block = 16 rows x 1024 j (full rows), 512 threads, thread = 4 rows x 8 j.
// AJ streamed in 4 x 64KB h-chunks, cp.async double buffer.
// edge_step: FADD2 (fma) + 2x FMNMX (alu) + FFMA2 (fma), movs elided by
// letting ptxas pair-allocate the float2 temp across asm boundaries.
// ---------------------------------------------------------------------------
__device__ __forceinline__ void edge_step(unsigned long long& acc,
                                          unsigned long long ai,
                                          unsigned long long aj,
                                          unsigned long long w)
{
    float2 t;
    asm("add.rn.f32x2 %0, %1, %2;"
        : "=l"(reinterpret_cast<unsigned long long&>(t)) : "l"(ai), "l"(aj));
    t.x = fmaxf(t.x, 0.0f);
    t.y = fmaxf(t.y, 0.0f);
    asm("fma.rn.f32x2 %0, %1, %2, %0;"
        : "+l"(acc) : "l"(reinterpret_cast<unsigned long long&>(t)), "l"(w));
}

__device__ __forceinline__ void cp_async16(uint32_t smem_addr, const void* gptr)
{
    asm volatile("cp.async.cg.shared.global [%0], [%1], 16;\n"
                 :: "r"(smem_addr), "l"(gptr));
}

#define ROWS 16
#define JT 1024
#define HC 4                 // h-pair chunks
#define HPC 8                // h-pairs per chunk
#define CHUNK_BYTES (HPC * JT * 8)          // 65536
// smem: buf0 | buf1 | AI (16*64*4) | w2 (256) | redM (256) | redS (256)
#define OFF_AI   (2 * CHUNK_BYTES)
#define OFF_W2   (OFF_AI + ROWS * HH * 4)
#define OFF_RM   (OFF_W2 + 256)
#define OFF_RS   (OFF_RM + 256)
#define EDGE_SMEM (OFF_RS + 256)

extern __shared__ unsigned char smem_raw[];

__global__ __launch_bounds__(512, 1) void edge_kernel(const int* __restrict__ visited,
                                                      const float* __restrict__ W2,
                                                      const float* __restrict__ b2,
                                                      float* __restrict__ out)
{
    float* AI_s = (float*)(smem_raw + OFF_AI);
    float* w2_s = (float*)(smem_raw + OFF_W2);
    float* redM = (float*)(smem_raw + OFF_RM);
    float* redS = (float*)(smem_raw + OFF_RS);

    const int tid = threadIdx.x;
    const int bi = blockIdx.x;
    const int b = bi >> 6;
    const int i0 = (bi & 63) * ROWS;

    const uint32_t smem_base = (uint32_t)__cvta_generic_to_shared(smem_raw);

    // Prefetch chunk 0 into buf0
    {
        const float* src = g_AJ + (size_t)b * (HH / 2) * NN * 2;
#pragma unroll
        for (int it = 0; it < CHUNK_BYTES / 16 / 512; it++)
            cp_async16(smem_base + (tid + it * 512) * 16, src + (tid + it * 512) * 4);
        asm volatile("cp.async.commit_group;\n");
    }

    // Stage AI tile + w2 while chunk 0 is in flight
    if (tid < ROWS * HH / 4) {
        const float4* src = (const float4*)(g_AI + (size_t)(b * NN + i0) * HH);
        ((float4*)AI_s)[tid] = src[tid];
    }
    if (tid < HH) w2_s[tid] = W2[tid];

    const int g = tid >> 7;        // row group 0..3
    const int lg = tid & 127;      // j lane 0..127
    const int w = (tid >> 5) & 3;  // warp within group
    const int rbase = g * 4;

    int vrow[4], vcol[8];
#pragma unroll
    for (int r = 0; r < 4; r++) vrow[r] = visited[b * NN + i0 + rbase + r];
#pragma unroll
    for (int k = 0; k < 8; k++) vcol[k] = visited[b * NN + lg + (k << 7)];
    const float b2v = b2[0];

    unsigned long long acc[4][8];
#pragma unroll
    for (int r = 0; r < 4; r++)
#pragma unroll
        for (int k = 0; k < 8; k++) acc[r][k] = 0ull;

#pragma unroll 1
    for (int hc = 0; hc < HC; hc++) {
        // wait for this chunk's cp.async group, then make it block-visible
        asm volatile("cp.async.wait_group 0;\n");
        __syncthreads();

        if (hc + 1 < HC) {
            const float* src = g_AJ + (size_t)b * (HH / 2) * NN * 2
                             + (size_t)(hc + 1) * HPC * NN * 2;
            const uint32_t dstb = smem_base + ((hc + 1) & 1) * CHUNK_BYTES;
#pragma unroll
            for (int it = 0; it < CHUNK_BYTES / 16 / 512; it++)
                cp_async16(dstb + (tid + it * 512) * 16, src + (tid + it * 512) * 4);
            asm volatile("cp.async.commit_group;\n");
        }

        const unsigned long long* buf =
            (const unsigned long long*)(smem_raw + (hc & 1) * CHUNK_BYTES);

#pragma unroll
        for (int p = 0; p < HPC; p++) {
            const unsigned long long w2p =
                *(const unsigned long long*)&w2_s[hc * 16 + 2 * p];
            unsigned long long aiv[4];
#pragma unroll
            for (int r = 0; r < 4; r++)
                aiv[r] = *(const unsigned long long*)&AI_s[(rbase + r) * HH + hc * 16 + 2 * p];
            unsigned long long aj[8];
#pragma unroll
            for (int k = 0; k < 8; k++)
                aj[k] = buf[p * JT + lg + (k << 7)];
#pragma unroll
            for (int k = 0; k < 8; k++)
#pragma unroll
                for (int r = 0; r < 4; r++)
                    edge_step(acc[r][k], aiv[r], aj[k], w2p);
        }
    }

    // ---- epilogue: unpack, mask, softmax over each full row, write out ----
    float v[4][8];
#pragma unroll
    for (int r = 0; r < 4; r++)
#pragma unroll
        for (int k = 0; k < 8; k++) {
            const float2 t = reinterpret_cast<const float2&>(acc[r][k]);
            const float s = t.x + t.y + b2v;
            v[r][k] = ((vrow[r] | vcol[k]) != 0) ? -1e9f : s;
        }

    // row max: thread-local -> warp -> 4 warps via smem
    float mloc[4];
#pragma unroll
    for (int r = 0; r < 4; r++) {
        float m = v[r][0];
#pragma unroll
        for (int k = 1; k < 8; k++) m = fmaxf(m, v[r][k]);
#pragma unroll
        for (int s = 16; s > 0; s >>= 1) m = fmaxf(m, __shfl_xor_sync(0xffffffffu, m, s));
        if ((tid & 31) == 0) redM[(g * 4 + r) * 4 + w] = m;
        mloc[r] = m;
    }
    __syncthreads();
#pragma unroll
    for (int r = 0; r < 4; r++) {
        const float* rm = &redM[(g * 4 + r) * 4];
        mloc[r] = fmaxf(fmaxf(rm[0], rm[1]), fmaxf(rm[2], rm[3]));
    }

    // exp + row sum
#pragma unroll
    for (int r = 0; r < 4; r++) {
        float s = 0.f;
#pragma unroll
        for (int k = 0; k < 8; k++) {
            v[r][k] = __expf(v[r][k] - mloc[r]);
            s += v[r][k];
        }
#pragma unroll
        for (int sh = 16; sh > 0; sh >>= 1) s += __shfl_xor_sync(0xffffffffu, s, sh);
        if ((tid & 31) == 0) redS[(g * 4 + r) * 4 + w] = s;
    }
    __syncthreads();
#pragma unroll
    for (int r = 0; r < 4; r++) {
        const float* rs = &redS[(g * 4 + r) * 4];
        const float inv = 1.0f / ((rs[0] + rs[1]) + (rs[2] + rs[3]));
        float* rowp = out + (size_t)(b * NN + i0 + rbase + r) * NN;
#pragma unroll
        for (int k = 0; k < 8; k++)
            rowp[lg + (k << 7)] = v[r][k] * inv;
    }
}

// ---------------------------------------------------------------------------
extern "C" void kernel_launch(void* const* d_in, const int* in_sizes, int n_in,
                              void* d_out, int out_size)
{
    const float* emb = (const float*)d_in[0];
    const int* visited = (const int*)d_in[1];
    // d_in[2] = remaining_capacity: unused by the reference
    const float* W1 = (const float*)d_in[3];
    const float* b1 = (const float*)d_in[4];
    const float* W2 = (const float*)d_in[5];
    const float* b2 = (const float*)d_in[6];
    float* out = (float*)d_out;

    proj_kernel<<<128, 512>>>(emb, W1, b1);

    cudaFuncSetAttribute((const void*)edge_kernel,
                         cudaFuncAttributeMaxDynamicSharedMemorySize, EDGE_SMEM);
    edge_kernel<<<128, 512, EDGE_SMEM>>>(visited, W2, b2, out);
}